// round 7
// baseline (speedup 1.0000x reference)
#include <cuda_runtime.h>
#include <stdint.h>

#define D 128
#define K 16
#define TPB 128
#define WARPS 4
#define WROWS 64                // rows per warp work-unit (R=2 per thread)
#define CH 16                   // columns per chunk
#define NCH 8                   // chunks per unit (D/CH)
#define ROWSTRIDE 80            // 64B data + 16B pad: conflict-free LDS.128, 16B aligned
#define STAGE_BYTES (WROWS * ROWSTRIDE)      // 5120
#define NSTAGE 2
#define WARP_STAGING (NSTAGE * STAGE_BYTES)  // 10240
#define SMEM_HDR 8448           // A (8192) + c/U + pad
#define SMEM_TOTAL (SMEM_HDR + WARPS * WARP_STAGING)  // 49408 -> 4 CTAs/SM at <=128 regs
#define NBLK 592                // persistent: 148 SMs x 4 CTAs

// Precomputed A in (cp, k) pair-major: gAp[cp*K + k] is float2 = (A[k][2cp], A[k][2cp+1])
__device__ __align__(16) float gAp[(D / 2) * K * 2];
__device__ float gC[K];

// ---------------- helpers ----------------
__device__ __forceinline__ void ffma2(unsigned long long& c, unsigned long long a, unsigned long long b) {
    asm("fma.rn.f32x2 %0, %1, %2, %0;" : "+l"(c) : "l"(a), "l"(b));
}
__device__ __forceinline__ void unpack2(float& lo, float& hi, unsigned long long v) {
    asm("mov.b64 {%0, %1}, %2;" : "=f"(lo), "=f"(hi) : "l"(v));
}
__device__ __forceinline__ void cp_async16(uint32_t dst, const void* src, int src_bytes) {
    asm volatile("cp.async.cg.shared.global [%0], [%1], 16, %2;\n"
                 :: "r"(dst), "l"(src), "r"(src_bytes));
}
__device__ __forceinline__ void cp_commit() {
    asm volatile("cp.async.commit_group;\n" ::: "memory");
}
__device__ __forceinline__ void cp_wait1() {
    asm volatile("cp.async.wait_group 1;\n" ::: "memory");
}
__device__ __forceinline__ ulonglong2 lds128(uint32_t addr) {
    ulonglong2 q;
    asm volatile("ld.shared.v2.u64 {%0,%1}, [%2];" : "=l"(q.x), "=l"(q.y) : "r"(addr));
    return q;
}

// ---------------- merged prep (single launch) ----------------
// blocks 0..127: A rows (warp computes 4 rows, MLP=4); block 128: c[k]
__global__ void ntn_prep(const float* __restrict__ x2,
                         const float* __restrict__ V,
                         const float* __restrict__ W,
                         const float* __restrict__ b) {
    const int lane = threadIdx.x & 31;
    const int wid = threadIdx.x >> 5;
    const float4 x4 = ((const float4*)x2)[lane];

    if (blockIdx.x < 128) {
        const int gw = blockIdx.x * 4 + wid;        // 0..511, rows 4gw..4gw+3
        float4 w4[4];
#pragma unroll
        for (int rr = 0; rr < 4; rr++)
            w4[rr] = ((const float4*)(W + (size_t)(gw * 4 + rr) * D))[lane];
        float dots[4];
#pragma unroll
        for (int rr = 0; rr < 4; rr++)
            dots[rr] = w4[rr].x * x4.x + w4[rr].y * x4.y + w4[rr].z * x4.z + w4[rr].w * x4.w;
#pragma unroll
        for (int s = 16; s > 0; s >>= 1) {
#pragma unroll
            for (int rr = 0; rr < 4; rr++)
                dots[rr] += __shfl_xor_sync(0xffffffffu, dots[rr], s);
        }
        if (lane == 0) {
#pragma unroll
            for (int rr = 0; rr < 4; rr++) {
                const int row = gw * 4 + rr;        // = k*128 + d
                const int k = row >> 7, d = row & (D - 1);
                gAp[((d >> 1) * K + k) * 2 + (d & 1)] = V[(size_t)k * 2 * D + d] + dots[rr];
            }
        }
    } else {
#pragma unroll
        for (int kk = 0; kk < 4; kk++) {
            const int k = wid * 4 + kk;
            const float4 v4 = ((const float4*)(V + (size_t)k * 2 * D + D))[lane];
            float dot = v4.x * x4.x + v4.y * x4.y + v4.z * x4.z + v4.w * x4.w;
#pragma unroll
            for (int s = 16; s > 0; s >>= 1)
                dot += __shfl_xor_sync(0xffffffffu, dot, s);
            if (lane == 0) gC[k] = dot + b[k];
        }
    }
}

// ---------------- main: persistent per-warp units, 2-stage per-warp cp.async pipeline ----------------
__global__ __launch_bounds__(TPB, 4)
void ntn_main(const float* __restrict__ x1,
              const float* __restrict__ U,
              float* __restrict__ out, int n, int nunits, int nw) {
    extern __shared__ __align__(16) char smem_raw[];
    unsigned long long* sA = (unsigned long long*)smem_raw;   // 1024 ull, cp-major
    float* sC = (float*)(smem_raw + 8192);
    float* sU = sC + K;

    const int tid = threadIdx.x;
    const int wid = tid >> 5;
    const int lane = tid & 31;

    const uint32_t smem_u32 = (uint32_t)__cvta_generic_to_shared(smem_raw);
    const uint32_t wstage_u32 = smem_u32 + SMEM_HDR + (uint32_t)wid * WARP_STAGING;
    const uint32_t xA_base = wstage_u32 + (uint32_t)lane * ROWSTRIDE;         // this thread's row a
    const uint32_t xB_base = wstage_u32 + (uint32_t)(lane + 32) * ROWSTRIDE;  // row b

    // per-lane cp.async geometry (computed once): 8 ops/lane per chunk (64 rows x 64B)
    // idx = i*32+lane ; r = idx>>2 (0..63) ; c = idx&3 (float4 within 64B)
    int r_[8]; uint32_t doff[8]; uint32_t soff[8];
#pragma unroll
    for (int i = 0; i < 8; i++) {
        const int idx = i * 32 + lane;
        r_[i] = idx >> 2;
        const int c = idx & 3;
        doff[i] = (uint32_t)(r_[i] * ROWSTRIDE + c * 16);
        soff[i] = (uint32_t)(r_[i] * (D * 4) + c * 16);
    }

    const int gw0 = blockIdx.x * WARPS + wid;

    // ---- per-unit state (srcbase + tail predicates), recomputed per unit ----
    const char* ub = (const char*)x1 + (size_t)gw0 * (WROWS * D * 4);
    int nb[8];
    {
        const int rlim = n - gw0 * WROWS;
#pragma unroll
        for (int i = 0; i < 8; i++) nb[i] = (r_[i] < rlim) ? 16 : 0;
    }

    // prologue: issue chunk 0 of first unit
    if (gw0 < nunits) {
#pragma unroll
        for (int i = 0; i < 8; i++) cp_async16(wstage_u32 + doff[i], ub + soff[i], nb[i]);
    }
    cp_commit();

    // header: A, c, U (single block barrier in whole kernel)
    {
        const unsigned long long* gAu = (const unsigned long long*)gAp;
#pragma unroll
        for (int i = 0; i < 8; i++) sA[tid + i * TPB] = gAu[tid + i * TPB];
        if (tid < K) { sC[tid] = gC[tid]; sU[tid] = U[tid]; }
    }
    __syncthreads();

    int buf = 0;
    for (int u = gw0; u < nunits; u += nw) {
        unsigned long long acc0[K], acc1[K];
#pragma unroll
        for (int k = 0; k < K; k++) { acc0[k] = 0ull; acc1[k] = 0ull; }

#pragma unroll 1
        for (int ch = 0; ch < NCH; ch++) {
            // issue the next chunk in the stream (next ch of this unit, or chunk 0 of next unit)
            if (ch < NCH - 1) {
                const uint32_t db = wstage_u32 + (uint32_t)(buf ^ 1) * STAGE_BYTES;
                const char* sb = ub + (ch + 1) * (CH * 4);
#pragma unroll
                for (int i = 0; i < 8; i++) cp_async16(db + doff[i], sb + soff[i], nb[i]);
            } else {
                const int u2 = u + nw;
                if (u2 < nunits) {
                    // advance per-unit state to next unit
                    ub = (const char*)x1 + (size_t)u2 * (WROWS * D * 4);
                    const int rlim = n - u2 * WROWS;
#pragma unroll
                    for (int i = 0; i < 8; i++) nb[i] = (r_[i] < rlim) ? 16 : 0;
                    const uint32_t db = wstage_u32 + (uint32_t)(buf ^ 1) * STAGE_BYTES;
#pragma unroll
                    for (int i = 0; i < 8; i++) cp_async16(db + doff[i], ub + soff[i], nb[i]);
                }
            }
            cp_commit();                 // every iter -> uniform group counting
            cp_wait1();                  // <=1 pending => current chunk landed

            const uint32_t bo = (uint32_t)buf * STAGE_BYTES + (uint32_t)ch * 0; // buf offset
            const uint32_t ra_p = xA_base + bo;
            const uint32_t rb_p = xB_base + bo;

#pragma unroll
            for (int half = 0; half < 2; half++) {
                // 32B of each row -> 8 ull live
                const ulonglong2 qa0 = lds128(ra_p + half * 32);
                const ulonglong2 qa1 = lds128(ra_p + half * 32 + 16);
                const ulonglong2 qb0 = lds128(rb_p + half * 32);
                const ulonglong2 qb1 = lds128(rb_p + half * 32 + 16);
                const unsigned long long xa[4] = { qa0.x, qa0.y, qa1.x, qa1.y };
                const unsigned long long xb[4] = { qb0.x, qb0.y, qb1.x, qb1.y };
#pragma unroll
                for (int cpl = 0; cpl < 4; cpl++) {
                    const ulonglong2* Ab = (const ulonglong2*)(sA + (ch * 8 + half * 4 + cpl) * K);
#pragma unroll
                    for (int k2 = 0; k2 < 8; k2++) {
                        const ulonglong2 a2 = Ab[k2];       // broadcast LDS.128 -> 4 FFMA2
                        ffma2(acc0[2 * k2],     xa[cpl], a2.x);
                        ffma2(acc0[2 * k2 + 1], xa[cpl], a2.y);
                        ffma2(acc1[2 * k2],     xb[cpl], a2.x);
                        ffma2(acc1[2 * k2 + 1], xb[cpl], a2.y);
                    }
                }
            }
            __syncwarp();               // WAR: all lanes done with buf before re-issue
            buf ^= 1;
        }

        // epilogue (next unit's chunk 0 already in flight)
        float res0 = 0.f, res1 = 0.f;
#pragma unroll
        for (int k = 0; k < K; k++) {
            float lo, hi;
            unpack2(lo, hi, acc0[k]);
            const float s0 = lo + hi + sC[k];
            res0 = fmaf(fmaxf(s0, 0.f), sU[k], res0);
            unpack2(lo, hi, acc1[k]);
            const float s1 = lo + hi + sC[k];
            res1 = fmaf(fmaxf(s1, 0.f), sU[k], res1);
        }
        const int ra = u * WROWS + lane;
        const int rb = ra + 32;
        if (ra < n) out[ra] = res0;
        if (rb < n) out[rb] = res1;
    }
    asm volatile("cp.async.wait_all;\n" ::: "memory");
}

// ---------------- launch ----------------
extern "C" void kernel_launch(void* const* d_in, const int* in_sizes, int n_in,
                              void* d_out, int out_size) {
    const float* x1 = nullptr; const float* x2 = nullptr; const float* V = nullptr;
    const float* W = nullptr;  const float* b = nullptr;  const float* U = nullptr;
    int n16 = 0;
    for (int i = 0; i < n_in; i++) {
        const int s = in_sizes[i];
        const float* p = (const float*)d_in[i];
        if (s == 128) x2 = p;
        else if (s == 4096) V = p;
        else if (s == 262144) W = p;
        else if (s == 16) { if (n16++ == 0) b = p; else U = p; }
        else x1 = p;
    }
    int n = 0;
    for (int i = 0; i < n_in; i++) if ((const float*)d_in[i] == x1) n = in_sizes[i] / D;

    float* out = (float*)d_out;

    ntn_prep<<<129, TPB>>>(x2, V, W, b);

    const int nunits = (n + WROWS - 1) / WROWS;
    int blocks = (nunits + WARPS - 1) / WARPS;
    if (blocks > NBLK) blocks = NBLK;
    const int nw = blocks * WARPS;
    cudaFuncSetAttribute(ntn_main, cudaFuncAttributeMaxDynamicSharedMemorySize, SMEM_TOTAL);
    ntn_main<<<blocks, TPB, SMEM_TOTAL>>>(x1, U, out, n, nunits, nw);
}

// round 8
// speedup vs baseline: 1.2287x; 1.2287x over previous
#include <cuda_runtime.h>
#include <stdint.h>

#define D 128
#define K 16
#define TPB 128
#define WARPS 4
#define WROWS 64                // rows per warp unit; lane-pair p owns rows p+16*rr
#define CH 16                   // columns per chunk
#define NCH 8                   // chunks per unit (D/CH)
#define ROWSTRIDE 80            // 64B data + 16B pad: conflict-free LDS.128, 16B aligned
#define STAGE_BYTES (WROWS * ROWSTRIDE)      // 5120
#define WARP_STAGING (2 * STAGE_BYTES)       // 2 stages
#define SMEM_HDR 8448           // A (8192) + c/U + pad
#define SMEM_TOTAL (SMEM_HDR + WARPS * WARP_STAGING)  // 49408 -> 4 CTAs/SM
#define NBLK 592                // persistent: 148 SMs x 4 CTAs

// Precomputed A in (cp, k) pair-major: ull index cp*16+k holds f32x2 (A[k][2cp],A[k][2cp+1])
__device__ __align__(16) float gAp[(D / 2) * K * 2];
__device__ float gC[K];

// ---------------- helpers ----------------
__device__ __forceinline__ void ffma2(unsigned long long& c, unsigned long long a, unsigned long long b) {
    asm("fma.rn.f32x2 %0, %1, %2, %0;" : "+l"(c) : "l"(a), "l"(b));
}
__device__ __forceinline__ void unpack2(float& lo, float& hi, unsigned long long v) {
    asm("mov.b64 {%0, %1}, %2;" : "=f"(lo), "=f"(hi) : "l"(v));
}
__device__ __forceinline__ void cp_async16(uint32_t dst, const void* src, int src_bytes) {
    asm volatile("cp.async.cg.shared.global [%0], [%1], 16, %2;\n"
                 :: "r"(dst), "l"(src), "r"(src_bytes));
}
__device__ __forceinline__ void cp_commit() {
    asm volatile("cp.async.commit_group;\n" ::: "memory");
}
__device__ __forceinline__ void cp_wait1() {
    asm volatile("cp.async.wait_group 1;\n" ::: "memory");
}
__device__ __forceinline__ ulonglong2 lds128(uint32_t addr) {
    ulonglong2 q;
    asm volatile("ld.shared.v2.u64 {%0,%1}, [%2];" : "=l"(q.x), "=l"(q.y) : "r"(addr));
    return q;
}

// ---------------- merged prep (single launch) ----------------
__global__ void ntn_prep(const float* __restrict__ x2,
                         const float* __restrict__ V,
                         const float* __restrict__ W,
                         const float* __restrict__ b) {
    const int lane = threadIdx.x & 31;
    const int wid = threadIdx.x >> 5;
    const float4 x4 = ((const float4*)x2)[lane];

    if (blockIdx.x < 128) {
        const int gw = blockIdx.x * 4 + wid;        // 0..511, rows 4gw..4gw+3
        float4 w4[4];
#pragma unroll
        for (int rr = 0; rr < 4; rr++)
            w4[rr] = ((const float4*)(W + (size_t)(gw * 4 + rr) * D))[lane];
        float dots[4];
#pragma unroll
        for (int rr = 0; rr < 4; rr++)
            dots[rr] = w4[rr].x * x4.x + w4[rr].y * x4.y + w4[rr].z * x4.z + w4[rr].w * x4.w;
#pragma unroll
        for (int s = 16; s > 0; s >>= 1) {
#pragma unroll
            for (int rr = 0; rr < 4; rr++)
                dots[rr] += __shfl_xor_sync(0xffffffffu, dots[rr], s);
        }
        if (lane == 0) {
#pragma unroll
            for (int rr = 0; rr < 4; rr++) {
                const int row = gw * 4 + rr;        // = k*128 + d
                const int k = row >> 7, d = row & (D - 1);
                gAp[((d >> 1) * K + k) * 2 + (d & 1)] = V[(size_t)k * 2 * D + d] + dots[rr];
            }
        }
    } else {
#pragma unroll
        for (int kk = 0; kk < 4; kk++) {
            const int k = wid * 4 + kk;
            const float4 v4 = ((const float4*)(V + (size_t)k * 2 * D + D))[lane];
            float dot = v4.x * x4.x + v4.y * x4.y + v4.z * x4.z + v4.w * x4.w;
#pragma unroll
            for (int s = 16; s > 0; s >>= 1)
                dot += __shfl_xor_sync(0xffffffffu, dot, s);
            if (lane == 0) gC[k] = dot + b[k];
        }
    }
}

// ---------------- main: persistent per-warp units, k-split x 4-row fragments ----------------
__global__ __launch_bounds__(TPB, 4)
void ntn_main(const float* __restrict__ x1,
              const float* __restrict__ U,
              float* __restrict__ out, int n, int nunits, int nw) {
    extern __shared__ __align__(16) char smem_raw[];
    unsigned long long* sA = (unsigned long long*)smem_raw;   // 1024 ull, cp-major
    float* sC = (float*)(smem_raw + 8192);
    float* sU = sC + K;

    const int tid = threadIdx.x;
    const int wid = tid >> 5;
    const int lane = tid & 31;
    const int h = lane & 1;          // k-half: 0 -> k 0..7, 1 -> k 8..15
    const int p = lane >> 1;         // row-pair id 0..15

    const uint32_t smem_u32 = (uint32_t)__cvta_generic_to_shared(smem_raw);
    const uint32_t sA_u32 = smem_u32;
    const uint32_t wstage_u32 = smem_u32 + SMEM_HDR + (uint32_t)wid * WARP_STAGING;
    const uint32_t xoff = (uint32_t)p * ROWSTRIDE;   // + rr*16*ROWSTRIDE per row

    // per-warp chunk issue: 64 rows x 16 cols (64B/row) -> 8 cp.async16 per lane (as R4)
    auto issue = [&](int unit, int ch, int buf) {
        const uint32_t base = wstage_u32 + (uint32_t)buf * STAGE_BYTES;
        const int rowbase = unit * WROWS;
#pragma unroll
        for (int i = 0; i < 8; i++) {
            const int idx = i * 32 + lane;
            const int r = idx >> 2;          // 0..63
            const int c = idx & 3;           // float4 within 64B row-chunk
            const int grow = rowbase + r;
            const int ok = (grow < n);
            const float* src = x1 + (size_t)(ok ? grow : 0) * D + ch * CH + c * 4;
            cp_async16(base + (uint32_t)(r * ROWSTRIDE + c * 16), src, ok ? 16 : 0);
        }
    };

    const int gw0 = blockIdx.x * WARPS + wid;

    // prologue: chunk 0 of first unit in flight before header load
    if (gw0 < nunits) { issue(gw0, 0, 0); }
    cp_commit();

    // header: A, c, U (single block barrier in whole kernel)
    {
        const unsigned long long* gAu = (const unsigned long long*)gAp;
#pragma unroll
        for (int i = 0; i < 8; i++) sA[tid + i * TPB] = gAu[tid + i * TPB];
        if (tid < K) { sC[tid] = gC[tid]; sU[tid] = U[tid]; }
    }
    __syncthreads();

    for (int u = gw0; u < nunits; u += nw) {
        unsigned long long acc[4][8];    // [row rr][k-pair j] ; k = h*8 + 2j{+1}
#pragma unroll
        for (int rr = 0; rr < 4; rr++)
#pragma unroll
            for (int j = 0; j < 8; j++) acc[rr][j] = 0ull;

        // one chunk: issue lookahead, wait, compute from buf
        auto chunk = [&](int ch, int buf) {
            // issue next chunk in the stream (next ch of this unit, or chunk 0 of next unit)
            if (ch < NCH - 1) {
                issue(u, ch + 1, buf ^ 1);
            } else {
                const int u2 = u + nw;
                if (u2 < nunits) issue(u2, 0, buf ^ 1);
            }
            cp_commit();
            cp_wait1();
            __syncwarp();

            const uint32_t wb = wstage_u32 + (uint32_t)buf * STAGE_BYTES + xoff;
#pragma unroll
            for (int q = 0; q < 4; q++) {          // 16B quads of the 64B chunk-row
                ulonglong2 xq[4];
#pragma unroll
                for (int rr = 0; rr < 4; rr++)
                    xq[rr] = lds128(wb + (uint32_t)(rr * 16 * ROWSTRIDE + q * 16));
#pragma unroll
                for (int e = 0; e < 2; e++) {      // col-pair within quad
                    const int cpl = q * 2 + e;
                    const uint32_t abase = sA_u32 + (uint32_t)(((ch * 8 + cpl) * 16 + h * 8) * 8);
#pragma unroll
                    for (int k2 = 0; k2 < 4; k2++) {
                        const ulonglong2 a2 = lds128(abase + (uint32_t)(k2 * 16));  // 2 k values
#pragma unroll
                        for (int rr = 0; rr < 4; rr++) {
                            const unsigned long long xv = e ? xq[rr].y : xq[rr].x;
                            ffma2(acc[rr][2 * k2],     xv, a2.x);
                            ffma2(acc[rr][2 * k2 + 1], xv, a2.y);
                        }
                    }
                }
            }
            __syncwarp();      // WAR: all lanes done with buf before it is re-issued
        };

#pragma unroll 1
        for (int ch2 = 0; ch2 < NCH; ch2 += 2) {   // manual 2x: static buffer parity
            chunk(ch2, 0);
            chunk(ch2 + 1, 1);
        }

        // epilogue: per-row partial over this lane's 8 k, combine across lane pair
#pragma unroll
        for (int rr = 0; rr < 4; rr++) {
            float part = 0.f;
#pragma unroll
            for (int j = 0; j < 8; j++) {
                float lo, hi;
                unpack2(lo, hi, acc[rr][j]);
                const int k = h * 8 + j;
                const float s = lo + hi + sC[k];
                part = fmaf(fmaxf(s, 0.f), sU[k], part);
            }
            const float tot = part + __shfl_xor_sync(0xffffffffu, part, 1);
            const int row = u * WROWS + rr * 16 + p;
            if (h == 0 && row < n) out[row] = tot;
        }
    }
    asm volatile("cp.async.wait_all;\n" ::: "memory");
}

// ---------------- launch ----------------
extern "C" void kernel_launch(void* const* d_in, const int* in_sizes, int n_in,
                              void* d_out, int out_size) {
    const float* x1 = nullptr; const float* x2 = nullptr; const float* V = nullptr;
    const float* W = nullptr;  const float* b = nullptr;  const float* U = nullptr;
    int n16 = 0;
    for (int i = 0; i < n_in; i++) {
        const int s = in_sizes[i];
        const float* p = (const float*)d_in[i];
        if (s == 128) x2 = p;
        else if (s == 4096) V = p;
        else if (s == 262144) W = p;
        else if (s == 16) { if (n16++ == 0) b = p; else U = p; }
        else x1 = p;
    }
    int n = 0;
    for (int i = 0; i < n_in; i++) if ((const float*)d_in[i] == x1) n = in_sizes[i] / D;

    float* out = (float*)d_out;

    ntn_prep<<<129, TPB>>>(x2, V, W, b);

    const int nunits = (n + WROWS - 1) / WROWS;
    int blocks = (nunits + WARPS - 1) / WARPS;
    if (blocks > NBLK) blocks = NBLK;
    const int nw = blocks * WARPS;
    cudaFuncSetAttribute(ntn_main, cudaFuncAttributeMaxDynamicSharedMemorySize, SMEM_TOTAL);
    ntn_main<<<blocks, TPB, SMEM_TOTAL>>>(x1, U, out, n, nunits, nw);
}

// round 9
// speedup vs baseline: 1.2689x; 1.0327x over previous
#include <cuda_runtime.h>
#include <stdint.h>

#define D 128
#define K 16
#define TPB 128
#define WARPS 4
#define WROWS 32                // rows per warp unit; lane-pair p owns rows p, p+16
#define CH 16                   // columns per chunk
#define NCH 8                   // chunks per unit (D/CH)
#define ROWSTRIDE 80            // 64B data + 16B pad: conflict-free LDS.128, 16B aligned
#define STAGE_BYTES (WROWS * ROWSTRIDE)      // 2560
#define WARP_STAGING (2 * STAGE_BYTES)       // 2 stages = 5120
#define SMEM_HDR 8448           // A (8192) + c/U + pad
#define SMEM_TOTAL (SMEM_HDR + WARPS * WARP_STAGING)  // 28928 -> 6+ CTAs/SM (reg-limited)
#define NBLK 888                // persistent: 148 SMs x 6 CTAs

// Precomputed A in (cp, k) pair-major: ull index cp*16+k holds f32x2 (A[k][2cp],A[k][2cp+1])
__device__ __align__(16) float gAp[(D / 2) * K * 2];
__device__ float gC[K];

// ---------------- helpers ----------------
__device__ __forceinline__ void ffma2(unsigned long long& c, unsigned long long a, unsigned long long b) {
    asm("fma.rn.f32x2 %0, %1, %2, %0;" : "+l"(c) : "l"(a), "l"(b));
}
__device__ __forceinline__ void unpack2(float& lo, float& hi, unsigned long long v) {
    asm("mov.b64 {%0, %1}, %2;" : "=f"(lo), "=f"(hi) : "l"(v));
}
__device__ __forceinline__ void cp_async16(uint32_t dst, const void* src, int src_bytes) {
    asm volatile("cp.async.cg.shared.global [%0], [%1], 16, %2;\n"
                 :: "r"(dst), "l"(src), "r"(src_bytes));
}
__device__ __forceinline__ void cp_commit() {
    asm volatile("cp.async.commit_group;\n" ::: "memory");
}
__device__ __forceinline__ void cp_wait1() {
    asm volatile("cp.async.wait_group 1;\n" ::: "memory");
}
__device__ __forceinline__ ulonglong2 lds128(uint32_t addr) {
    ulonglong2 q;
    asm volatile("ld.shared.v2.u64 {%0,%1}, [%2];" : "=l"(q.x), "=l"(q.y) : "r"(addr));
    return q;
}

// ---------------- merged prep (single launch) ----------------
__global__ void ntn_prep(const float* __restrict__ x2,
                         const float* __restrict__ V,
                         const float* __restrict__ W,
                         const float* __restrict__ b) {
    const int lane = threadIdx.x & 31;
    const int wid = threadIdx.x >> 5;
    const float4 x4 = ((const float4*)x2)[lane];

    if (blockIdx.x < 128) {
        const int gw = blockIdx.x * 4 + wid;        // 0..511, rows 4gw..4gw+3
        float4 w4[4];
#pragma unroll
        for (int rr = 0; rr < 4; rr++)
            w4[rr] = ((const float4*)(W + (size_t)(gw * 4 + rr) * D))[lane];
        float dots[4];
#pragma unroll
        for (int rr = 0; rr < 4; rr++)
            dots[rr] = w4[rr].x * x4.x + w4[rr].y * x4.y + w4[rr].z * x4.z + w4[rr].w * x4.w;
#pragma unroll
        for (int s = 16; s > 0; s >>= 1) {
#pragma unroll
            for (int rr = 0; rr < 4; rr++)
                dots[rr] += __shfl_xor_sync(0xffffffffu, dots[rr], s);
        }
        if (lane == 0) {
#pragma unroll
            for (int rr = 0; rr < 4; rr++) {
                const int row = gw * 4 + rr;        // = k*128 + d
                const int k = row >> 7, d = row & (D - 1);
                gAp[((d >> 1) * K + k) * 2 + (d & 1)] = V[(size_t)k * 2 * D + d] + dots[rr];
            }
        }
    } else {
#pragma unroll
        for (int kk = 0; kk < 4; kk++) {
            const int k = wid * 4 + kk;
            const float4 v4 = ((const float4*)(V + (size_t)k * 2 * D + D))[lane];
            float dot = v4.x * x4.x + v4.y * x4.y + v4.z * x4.z + v4.w * x4.w;
#pragma unroll
            for (int s = 16; s > 0; s >>= 1)
                dot += __shfl_xor_sync(0xffffffffu, dot, s);
            if (lane == 0) gC[k] = dot + b[k];
        }
    }
}

// ---------------- main: persistent per-warp units, k-split x 2-row fragments, high occupancy ----------------
__global__ __launch_bounds__(TPB, 6)
void ntn_main(const float* __restrict__ x1,
              const float* __restrict__ U,
              float* __restrict__ out, int n, int nunits, int nw) {
    extern __shared__ __align__(16) char smem_raw[];
    unsigned long long* sA = (unsigned long long*)smem_raw;   // 1024 ull, cp-major
    float* sC = (float*)(smem_raw + 8192);
    float* sU = sC + K;

    const int tid = threadIdx.x;
    const int wid = tid >> 5;
    const int lane = tid & 31;
    const int h = lane & 1;          // k-half: 0 -> k 0..7, 1 -> k 8..15
    const int p = lane >> 1;         // row-pair id 0..15

    const uint32_t smem_u32 = (uint32_t)__cvta_generic_to_shared(smem_raw);
    const uint32_t sA_u32 = smem_u32;
    const uint32_t wstage_u32 = smem_u32 + SMEM_HDR + (uint32_t)wid * WARP_STAGING;
    const uint32_t xoff = (uint32_t)p * ROWSTRIDE;   // rows p and p+16 (+16*ROWSTRIDE)

    // per-warp chunk issue: 32 rows x 16 cols (64B/row) -> 4 cp.async16 per lane
    auto issue = [&](int unit, int ch, int buf) {
        const uint32_t base = wstage_u32 + (uint32_t)buf * STAGE_BYTES;
        const int rowbase = unit * WROWS;
#pragma unroll
        for (int i = 0; i < 4; i++) {
            const int idx = i * 32 + lane;
            const int r = idx >> 2;          // 0..31
            const int c = idx & 3;           // float4 within 64B row-chunk
            const int grow = rowbase + r;
            const int ok = (grow < n);
            const float* src = x1 + (size_t)(ok ? grow : 0) * D + ch * CH + c * 4;
            cp_async16(base + (uint32_t)(r * ROWSTRIDE + c * 16), src, ok ? 16 : 0);
        }
    };

    const int gw0 = blockIdx.x * WARPS + wid;

    // prologue: chunk 0 of first unit in flight before header load
    if (gw0 < nunits) { issue(gw0, 0, 0); }
    cp_commit();

    // header: A, c, U (single block barrier in whole kernel)
    {
        const unsigned long long* gAu = (const unsigned long long*)gAp;
#pragma unroll
        for (int i = 0; i < 8; i++) sA[tid + i * TPB] = gAu[tid + i * TPB];
        if (tid < K) { sC[tid] = gC[tid]; sU[tid] = U[tid]; }
    }
    __syncthreads();

    for (int u = gw0; u < nunits; u += nw) {
        unsigned long long acc[2][8];    // [row rr][k-pair j] ; k = h*8 + 2j{+1}
#pragma unroll
        for (int rr = 0; rr < 2; rr++)
#pragma unroll
            for (int j = 0; j < 8; j++) acc[rr][j] = 0ull;

        // one chunk: issue lookahead, wait, compute from buf
        auto chunk = [&](int ch, int buf) {
            if (ch < NCH - 1) {
                issue(u, ch + 1, buf ^ 1);
            } else {
                const int u2 = u + nw;
                if (u2 < nunits) issue(u2, 0, buf ^ 1);
            }
            cp_commit();
            cp_wait1();
            __syncwarp();

            const uint32_t wb = wstage_u32 + (uint32_t)buf * STAGE_BYTES + xoff;
#pragma unroll
            for (int q = 0; q < 4; q++) {          // 16B quads of the 64B chunk-row
                ulonglong2 xq[2];
                xq[0] = lds128(wb + (uint32_t)(q * 16));
                xq[1] = lds128(wb + (uint32_t)(16 * ROWSTRIDE + q * 16));
#pragma unroll
                for (int e = 0; e < 2; e++) {      // col-pair within quad
                    const int cpl = q * 2 + e;
                    const uint32_t abase = sA_u32 + (uint32_t)(((ch * 8 + cpl) * 16 + h * 8) * 8);
#pragma unroll
                    for (int k2 = 0; k2 < 4; k2++) {
                        const ulonglong2 a2 = lds128(abase + (uint32_t)(k2 * 16));  // 2 k values
#pragma unroll
                        for (int rr = 0; rr < 2; rr++) {
                            const unsigned long long xv = e ? xq[rr].y : xq[rr].x;
                            ffma2(acc[rr][2 * k2],     xv, a2.x);
                            ffma2(acc[rr][2 * k2 + 1], xv, a2.y);
                        }
                    }
                }
            }
            __syncwarp();      // WAR: all lanes done with buf before it is re-issued
        };

#pragma unroll 1
        for (int ch2 = 0; ch2 < NCH; ch2 += 2) {   // manual 2x: static buffer parity
            chunk(ch2, 0);
            chunk(ch2 + 1, 1);
        }

        // epilogue: per-row partial over this lane's 8 k, combine across lane pair
#pragma unroll
        for (int rr = 0; rr < 2; rr++) {
            float part = 0.f;
#pragma unroll
            for (int j = 0; j < 8; j++) {
                float lo, hi;
                unpack2(lo, hi, acc[rr][j]);
                const int k = h * 8 + j;
                const float s = lo + hi + sC[k];
                part = fmaf(fmaxf(s, 0.f), sU[k], part);
            }
            const float tot = part + __shfl_xor_sync(0xffffffffu, part, 1);
            const int row = u * WROWS + rr * 16 + p;
            if (h == 0 && row < n) out[row] = tot;
        }
    }
    asm volatile("cp.async.wait_all;\n" ::: "memory");
}

// ---------------- launch ----------------
extern "C" void kernel_launch(void* const* d_in, const int* in_sizes, int n_in,
                              void* d_out, int out_size) {
    const float* x1 = nullptr; const float* x2 = nullptr; const float* V = nullptr;
    const float* W = nullptr;  const float* b = nullptr;  const float* U = nullptr;
    int n16 = 0;
    for (int i = 0; i < n_in; i++) {
        const int s = in_sizes[i];
        const float* p = (const float*)d_in[i];
        if (s == 128) x2 = p;
        else if (s == 4096) V = p;
        else if (s == 262144) W = p;
        else if (s == 16) { if (n16++ == 0) b = p; else U = p; }
        else x1 = p;
    }
    int n = 0;
    for (int i = 0; i < n_in; i++) if ((const float*)d_in[i] == x1) n = in_sizes[i] / D;

    float* out = (float*)d_out;

    ntn_prep<<<129, TPB>>>(x2, V, W, b);

    const int nunits = (n + WROWS - 1) / WROWS;
    int blocks = (nunits + WARPS - 1) / WARPS;
    if (blocks > NBLK) blocks = NBLK;
    const int nw = blocks * WARPS;
    cudaFuncSetAttribute(ntn_main, cudaFuncAttributeMaxDynamicSharedMemorySize, SMEM_TOTAL);
    ntn_main<<<blocks, TPB, SMEM_TOTAL>>>(x1, U, out, n, nunits, nw);
}